// round 8
// baseline (speedup 1.0000x reference)
#include <cuda_runtime.h>

// LIF scan: T=16, N = 4,194,304 sites. HBM-bound streaming (256 MiB in, 256 MiB out).
// Roofline-pinned at ~6.3 TB/s (80% of spec) across 7 structurally different
// variants: occupancy, MLP, R/W phasing, wave structure, row locality, and L2
// write policy are all non-binding. Traffic is provably minimal.
//
// R8: final micro-sample — R2 body (TBATCH=8, .cs loads+stores) at block=512 /
// grid=2048 (midpoint of the 256/1024 CTA-geometry axis; perturbs L2-die-hash
// footprint per CTA and CTA->SM packing). Expected neutral; R2 is the fallback.

#ifndef LIF_T
#define LIF_T 16
#endif
#define TBATCH 8

__global__ void __launch_bounds__(512) lif_kernel(
    const float4* __restrict__ in,   // [T, N/4] float4
    float4* __restrict__ out,        // [T, N/4] float4
    int n4)                          // N/4
{
    const int i = blockIdx.x * blockDim.x + threadIdx.x;
    if (i >= n4) return;

    const float decay = 0.5f;
    const float thr   = 1.0f;

    float vx = 0.0f, vy = 0.0f, vz = 0.0f, vw = 0.0f;

    const float4* __restrict__ ip = in + i;
    float4* __restrict__ op = out + i;

    #pragma unroll
    for (int tb = 0; tb < LIF_T; tb += TBATCH) {
        // Phase 1: 8 front-batched streaming loads (independent LDG.128)
        float4 x[TBATCH];
        #pragma unroll
        for (int j = 0; j < TBATCH; ++j) {
            x[j] = __ldcs(ip + (size_t)(tb + j) * n4);
        }

        // Phase 2: serial LIF chain entirely in registers
        #pragma unroll
        for (int j = 0; j < TBATCH; ++j) {
            vx = fmaf(vx, decay, x[j].x);
            vy = fmaf(vy, decay, x[j].y);
            vz = fmaf(vz, decay, x[j].z);
            vw = fmaf(vw, decay, x[j].w);

            const float sx = (vx >= thr) ? 1.0f : 0.0f;
            const float sy = (vy >= thr) ? 1.0f : 0.0f;
            const float sz = (vz >= thr) ? 1.0f : 0.0f;
            const float sw = (vw >= thr) ? 1.0f : 0.0f;

            vx -= sx * thr;
            vy -= sy * thr;
            vz -= sz * thr;
            vw -= sw * thr;

            x[j].x = sx; x[j].y = sy; x[j].z = sz; x[j].w = sw;
        }

        // Phase 3: 8 batched streaming stores (STG.128)
        #pragma unroll
        for (int j = 0; j < TBATCH; ++j) {
            __stcs(op + (size_t)(tb + j) * n4, x[j]);
        }
    }
}

extern "C" void kernel_launch(void* const* d_in, const int* in_sizes, int n_in,
                              void* d_out, int out_size)
{
    const float* in = (const float*)d_in[0];
    float* out = (float*)d_out;

    const int total = in_sizes[0];            // T * N = 67,108,864
    const int n = total / LIF_T;              // N = 4,194,304 (sites)
    const int n4 = n / 4;                     // 1,048,576 float4 lanes

    const int block = 512;
    const int grid = (n4 + block - 1) / block;   // 2048

    lif_kernel<<<grid, block>>>((const float4*)in, (float4*)out, n4);
}

// round 9
// speedup vs baseline: 1.0124x; 1.0124x over previous
#include <cuda_runtime.h>

// LIF scan: T=16, N = 4,194,304 sites. HBM-bound streaming (256 MiB in, 256 MiB out).
// FINAL — roofline-pinned. Eight structurally different variants across 8
// rounds (occupancy 31-85%, per-thread MLP 2-16, interleaved vs phased R/W,
// 1 vs 3.5 waves, 4-16 KiB per-CTA row footprint, .cs vs default stores,
// block 256/512/1024) ALL pin at 6.27-6.36 TB/s (~80% of 8 TB/s spec).
// Traffic is provably minimal (serial recurrence: exactly one read + one
// write per element, zero exploitable reuse); compute/issue < 11%. The
// residual 20% is HBM controller-level (refresh + 50/50 R/W turnaround),
// not addressable from the SM.
//
// Config (best measured: ncu 76.0us, bench 82.4us): one thread per 4 sites
// (float4), time loop in 2 groups of 8: 8 front-batched LDG.128 ->
// serial v-chain in registers -> 8 batched STG.128, .cs hints both ways.

#ifndef LIF_T
#define LIF_T 16
#endif
#define TBATCH 8

__global__ void __launch_bounds__(256) lif_kernel(
    const float4* __restrict__ in,   // [T, N/4] float4
    float4* __restrict__ out,        // [T, N/4] float4
    int n4)                          // N/4
{
    const int i = blockIdx.x * blockDim.x + threadIdx.x;
    if (i >= n4) return;

    const float decay = 0.5f;
    const float thr   = 1.0f;

    float vx = 0.0f, vy = 0.0f, vz = 0.0f, vw = 0.0f;

    const float4* __restrict__ ip = in + i;
    float4* __restrict__ op = out + i;

    #pragma unroll
    for (int tb = 0; tb < LIF_T; tb += TBATCH) {
        // Phase 1: 8 front-batched streaming loads (independent LDG.128)
        float4 x[TBATCH];
        #pragma unroll
        for (int j = 0; j < TBATCH; ++j) {
            x[j] = __ldcs(ip + (size_t)(tb + j) * n4);
        }

        // Phase 2: serial LIF chain entirely in registers
        #pragma unroll
        for (int j = 0; j < TBATCH; ++j) {
            vx = fmaf(vx, decay, x[j].x);
            vy = fmaf(vy, decay, x[j].y);
            vz = fmaf(vz, decay, x[j].z);
            vw = fmaf(vw, decay, x[j].w);

            const float sx = (vx >= thr) ? 1.0f : 0.0f;
            const float sy = (vy >= thr) ? 1.0f : 0.0f;
            const float sz = (vz >= thr) ? 1.0f : 0.0f;
            const float sw = (vw >= thr) ? 1.0f : 0.0f;

            vx -= sx * thr;
            vy -= sy * thr;
            vz -= sz * thr;
            vw -= sw * thr;

            x[j].x = sx; x[j].y = sy; x[j].z = sz; x[j].w = sw;
        }

        // Phase 3: 8 batched streaming stores (STG.128)
        #pragma unroll
        for (int j = 0; j < TBATCH; ++j) {
            __stcs(op + (size_t)(tb + j) * n4, x[j]);
        }
    }
}

extern "C" void kernel_launch(void* const* d_in, const int* in_sizes, int n_in,
                              void* d_out, int out_size)
{
    const float* in = (const float*)d_in[0];
    float* out = (float*)d_out;

    const int total = in_sizes[0];            // T * N = 67,108,864
    const int n = total / LIF_T;              // N = 4,194,304 (sites)
    const int n4 = n / 4;                     // 1,048,576 float4 lanes

    const int block = 256;
    const int grid = (n4 + block - 1) / block;   // 4096

    lif_kernel<<<grid, block>>>((const float4*)in, (float4*)out, n4);
}